// round 14
// baseline (speedup 1.0000x reference)
#include <cuda_runtime.h>

// Problem constants: B=4, M=8, N=128, D=32, 2D=64, H=64. BM = B*M = 32 sets.
#define NSET 32
#define NN   128
#define DD   32
#define DD2  64

// Padded strides: 17 float4 = 272 B row stride => 4-bank skew, conflict-free.
#define A1S_STRIDE4 17
#define DS_STRIDE   68

typedef unsigned long long u64;

// Scratch (device globals -- no allocation allowed)
__device__ float g_x1[NSET * NN * DD];
__device__ float g_A1[NSET * NN * DD2];
__device__ float g_A2[NSET * NN * DD2];
__device__ float g_mask[NSET * NN];
__device__ float g_s[NSET * NN * NN];      // pair scores s[set][i][j] (2 MB)
__device__ int   g_nv[NSET];               // valid prefix length per set

// ---------------- packed f32x2 helpers (sm_103a) ----------------
__device__ __forceinline__ u64 f2add(u64 a, u64 b) {
    u64 r; asm("add.rn.f32x2 %0,%1,%2;" : "=l"(r) : "l"(a), "l"(b)); return r;
}
__device__ __forceinline__ u64 f2mul(u64 a, u64 b) {
    u64 r; asm("mul.rn.f32x2 %0,%1,%2;" : "=l"(r) : "l"(a), "l"(b)); return r;
}
__device__ __forceinline__ u64 f2fma(u64 a, u64 b, u64 c) {
    u64 r; asm("fma.rn.f32x2 %0,%1,%2,%3;" : "=l"(r) : "l"(a), "l"(b), "l"(c)); return r;
}
__device__ __forceinline__ u64 f2pack(float lo, float hi) {
    u64 r; asm("mov.b64 %0,{%1,%2};" : "=l"(r) : "f"(lo), "f"(hi)); return r;
}
__device__ __forceinline__ void f2unpack(float& lo, float& hi, u64 v) {
    asm("mov.b64 {%0,%1},%2;" : "=f"(lo), "=f"(hi) : "l"(v));
}
__device__ __forceinline__ float tanh_ap(float x) {
    float r; asm("tanh.approx.f32 %0,%1;" : "=f"(r) : "f"(x)); return r;
}

// scalar gelu (jax tanh form) via tanh.approx.
__device__ __forceinline__ float gelu_f(float t) {
    float u  = t * t;
    float z  = t * fmaf(0.0356774081f, u, 0.7978845608f);
    float th = tanh_ap(z);
    float ht = 0.5f * t;
    return fmaf(th, ht, ht);
}

// Nonlinear part of gelu-dot: packed math computes z and w = 0.5*v*t;
// scalar FMAs accumulate tanh(z)*w. Linear part factored into P[i]+Q[j].
__device__ __forceinline__ void gelu2_nl2(u64 a, u64 d, u64 hv,
                                          float& accl, float& acch,
                                          u64 C1, u64 C2) {
    u64 t = f2add(a, d);
    u64 u = f2mul(t, t);
    u64 p = f2fma(C1, u, C2);
    u64 z = f2mul(t, p);
    u64 w = f2mul(t, hv);
    float zl, zh; f2unpack(zl, zh, z);
    float wl, wh; f2unpack(wl, wh, w);
    accl = fmaf(tanh_ap(zl), wl, accl);
    acch = fmaf(tanh_ap(zh), wh, acch);
}

// ---------------------------------------------------------------------------
// Kernel 1: per-set norm stats + set_norm + MLP1 + A1/A2 precompute + Nv.
// grid = NSET * 8 blocks (one set x 16 rows each), 256 threads.
// ---------------------------------------------------------------------------
__global__ __launch_bounds__(256) void k1(
    const float* __restrict__ x, const float* __restrict__ x_size,
    const float* __restrict__ W1a, const float* __restrict__ b1a,
    const float* __restrict__ W1b, const float* __restrict__ b1b,
    const float* __restrict__ W2a)
{
    __shared__ float xs[NN * DD];
    __shared__ float w1a[DD * DD2];
    __shared__ float w1b[DD2 * DD];
    __shared__ float w2a[DD * DD2];
    __shared__ float xn[16 * DD];
    __shared__ float maskS[NN];
    __shared__ float red[8];
    __shared__ float statS[2];

    const int bm   = blockIdx.x >> 3;
    const int tile = blockIdx.x & 7;
    const int r0   = tile * 16;
    const int tid  = threadIdx.x;

    const float4* xg  = (const float4*)(x + bm * (NN * DD));
    float4*       xs4 = (float4*)xs;
    float lsum = 0.f;
    #pragma unroll
    for (int i = tid; i < 1024; i += 256) {
        float4 v = xg[i];
        xs4[i] = v;
        lsum += v.x + v.y + v.z + v.w;
    }
    #pragma unroll
    for (int i = tid; i < 512; i += 256) ((float4*)w1a)[i] = ((const float4*)W1a)[i];
    #pragma unroll
    for (int i = tid; i < 512; i += 256) ((float4*)w1b)[i] = ((const float4*)W1b)[i];
    #pragma unroll
    for (int i = tid; i < 512; i += 256) ((float4*)w2a)[i] = ((const float4*)W2a)[i];
    __syncthreads();

    if (tid < NN) {
        const float* row = xs + tid * DD;
        float m = 0.f;
        #pragma unroll
        for (int e = 0; e < DD; e++) if (row[e] != 0.f) { m = 1.f; break; }
        maskS[tid] = m;
    }
    #pragma unroll
    for (int o = 16; o; o >>= 1) lsum += __shfl_xor_sync(0xffffffffu, lsum, o);
    if ((tid & 31) == 0) red[tid >> 5] = lsum;
    __syncthreads();
    const float denom = x_size[bm >> 3] * (float)DD;
    if (tid == 0) {
        float s = 0.f;
        #pragma unroll
        for (int w = 0; w < 8; w++) s += red[w];
        statS[0] = s / denom;
    }
    // Nv = 1 + last index with mask=1 (maskS visible after the barrier above)
    if (tid < 32) {
        int mx = -1;
        #pragma unroll
        for (int c = 0; c < 4; c++) {
            unsigned bal = __ballot_sync(0xffffffffu, maskS[c * 32 + tid] != 0.f);
            if (bal) { int hi = 31 - __clz((int)bal); if (c * 32 + hi > mx) mx = c * 32 + hi; }
        }
        if (tid == 0) g_nv[bm] = mx + 1;
    }
    __syncthreads();
    const float mean = statS[0];

    float lss = 0.f;
    #pragma unroll
    for (int i = tid; i < 1024; i += 256) {
        float4 v = xs4[i];
        float m = maskS[i >> 3];
        float a = v.x - mean, b = v.y - mean, c = v.z - mean, d = v.w - mean;
        lss += (a * a + b * b + c * c + d * d) * m;
    }
    #pragma unroll
    for (int o = 16; o; o >>= 1) lss += __shfl_xor_sync(0xffffffffu, lss, o);
    if ((tid & 31) == 0) red[tid >> 5] = lss;
    __syncthreads();
    if (tid == 0) {
        float s = 0.f;
        #pragma unroll
        for (int w = 0; w < 8; w++) s += red[w];
        statS[1] = 1.0f / (sqrtf(s / denom) + 1e-8f);
    }
    __syncthreads();
    const float inv = statS[1];

    #pragma unroll
    for (int i = tid; i < 512; i += 256) {
        int n = r0 + (i >> 5);
        int e = i & 31;
        xn[i] = (xs[n * DD + e] - mean) * inv * maskS[n];
    }
    if (tid < 16) g_mask[bm * NN + r0 + tid] = maskS[r0 + tid];
    __syncthreads();

    float* hb  = xs;          // 16*64
    float* x1b = xs + 1024;   // 16*32

    #pragma unroll
    for (int i = tid; i < 1024; i += 256) {
        int n = i >> 6, k = i & 63;
        float acc = b1a[k];
        #pragma unroll
        for (int e = 0; e < DD; e++) acc = fmaf(xn[n * DD + e], w1a[e * DD2 + k], acc);
        hb[i] = gelu_f(acc);
    }
    __syncthreads();

    #pragma unroll
    for (int i = tid; i < 512; i += 256) {
        int n = i >> 5, d = i & 31;
        float acc = b1b[d];
        #pragma unroll
        for (int k = 0; k < DD2; k++) acc = fmaf(hb[n * DD2 + k], w1b[k * DD + d], acc);
        acc *= maskS[r0 + n];
        x1b[i] = acc;
        g_x1[bm * (NN * DD) + (r0 + n) * DD + d] = acc;
    }
    __syncthreads();

    #pragma unroll
    for (int i = tid; i < 1024; i += 256) {
        int n = i >> 6, k = i & 63;
        float a1 = 0.f, a2 = 0.f;
        #pragma unroll
        for (int e = 0; e < DD; e++) {
            float w = w2a[e * DD2 + k];
            a1 = fmaf(x1b[n * DD + e], w, a1);
            a2 = fmaf(xn[n * DD + e], w, a2);
        }
        g_A1[bm * (NN * DD2) + (r0 + n) * DD2 + k] = a1;
        g_A2[bm * (NN * DD2) + (r0 + n) * DD2 + k] = a2;
    }
}

// ---------------------------------------------------------------------------
// Kernel 2a: pair scores only -> g_s. grid = NSET * 8 jtiles * 2 ihalves = 512,
// 512 threads, 3 CTAs/SM. Thread owns j = tid&15 and 2 i's in its half.
// s[i,j] = P[i] + Q[j] + c + Sum_k (0.5 v_k t) * tanh(z(t)),  t = A1+d.
// ---------------------------------------------------------------------------
__global__ __launch_bounds__(512, 3) void k2a(
    const float* __restrict__ b2a, const float* __restrict__ W2b,
    const float* __restrict__ b2b, const float* __restrict__ w3)
{
    __shared__ float A1s[64 * A1S_STRIDE4 * 4];   // this i-half's rows, 17.4 KB
    __shared__ float dS[16 * DS_STRIDE];          // b2a[k] - A2[j0+j][k]
    __shared__ float vS[DD2];                     // 0.5 * (W2b @ w3)
    __shared__ float PS[64];
    __shared__ float QS[16];
    __shared__ float cS;

    const int bm  = blockIdx.x >> 4;
    const int sub = blockIdx.x & 15;
    const int jt  = sub & 7;
    const int ih  = sub >> 3;
    const int j0  = jt * 16;
    const int i0  = ih * 64;
    const int tid = threadIdx.x;

    const int Nv = g_nv[bm];
    if (j0 >= Nv || i0 >= Nv) return;   // outputs unread / masked downstream

    // --- stage A1 half (padded rows), dS, half-v, c ---
    const float4* a1g  = (const float4*)(g_A1 + bm * (NN * DD2) + i0 * DD2);
    float4*       A1s4 = (float4*)A1s;
    #pragma unroll
    for (int idx = tid; idx < 1024; idx += 512) {
        int i  = idx >> 4;
        int k4 = idx & 15;
        A1s4[i * A1S_STRIDE4 + k4] = a1g[idx];
    }
    #pragma unroll
    for (int i = tid; i < 1024; i += 512) {
        int jj = i >> 6, k = i & 63;
        dS[jj * DS_STRIDE + k] = b2a[k] - g_A2[bm * (NN * DD2) + (j0 + jj) * DD2 + k];
    }
    if (tid >= 448) {   // 64 threads: half-v
        int kk = tid - 448;
        float acc = 0.f;
        #pragma unroll
        for (int h = 0; h < 64; h++) acc = fmaf(W2b[kk * 64 + h], w3[h], acc);
        vS[kk] = 0.5f * acc;
    }
    if (tid == 0) {
        float acc = 0.f;
        #pragma unroll
        for (int h = 0; h < 64; h++) acc = fmaf(b2b[h], w3[h], acc);
        cS = acc;
    }
    __syncthreads();

    // --- P (local 64 rows) and Q; vS holds 0.5*v ---
    if (tid < 64) {
        const float* row = A1s + tid * (A1S_STRIDE4 * 4);
        float acc = 0.f;
        #pragma unroll
        for (int k = 0; k < DD2; k++) acc = fmaf(row[k], vS[k], acc);
        PS[tid] = acc;
    } else if (tid < 80) {
        int jj = tid - 64;
        const float* row = dS + jj * DS_STRIDE;
        float acc = 0.f;
        #pragma unroll
        for (int k = 0; k < DD2; k++) acc = fmaf(row[k], vS[k], acc);
        QS[jj] = acc;
    }
    __syncthreads();

    // --- pair phase: thread owns j = tid&15 and 2 local i's (bi, bi+32) ---
    const int j  = tid & 15;
    const int bi = tid >> 4;     // 0..31
    const ulonglong2* A1s2 = (const ulonglong2*)A1s;
    const ulonglong2* dj2  = (const ulonglong2*)(dS + j * DS_STRIDE);
    const ulonglong2* vv2  = (const ulonglong2*)vS;

    const u64 C1 = f2pack(0.0356774081f, 0.0356774081f);
    const u64 C2 = f2pack(0.7978845608f, 0.7978845608f);

    float a0l = 0.f, a0h = 0.f, a1l = 0.f, a1h = 0.f;
    #pragma unroll
    for (int k4 = 0; k4 < 16; k4++) {
        ulonglong2 dd = dj2[k4];
        ulonglong2 hv = vv2[k4];
        ulonglong2 q;
        q = A1s2[(bi      ) * A1S_STRIDE4 + k4];
        gelu2_nl2(q.x, dd.x, hv.x, a0l, a0h, C1, C2);
        gelu2_nl2(q.y, dd.y, hv.y, a0l, a0h, C1, C2);
        q = A1s2[(bi + 32) * A1S_STRIDE4 + k4];
        gelu2_nl2(q.x, dd.x, hv.x, a1l, a1h, C1, C2);
        gelu2_nl2(q.y, dd.y, hv.y, a1l, a1h, C1, C2);
    }
    {
        const float base = cS + QS[j];
        float* sp = g_s + bm * (NN * NN) + j0 + j;
        sp[(i0 + bi     ) * NN] = base + PS[bi     ] + a0l + a0h;
        sp[(i0 + bi + 32) * NN] = base + PS[bi + 32] + a1l + a1h;
    }
}

// ---------------------------------------------------------------------------
// Kernel 2b: aggregation. grid = NSET * 4 (32 j per block), 512 threads.
// out[j,d] = Sum_{i<Nv} s[i,j]*x1[i,d] + b3 + x[j,d], masked.
// ---------------------------------------------------------------------------
__global__ __launch_bounds__(512) void k2b(
    const float* __restrict__ x, const float* __restrict__ b3,
    float* __restrict__ out)
{
    __shared__ float x1s[NN * DD];    // 16 KB
    __shared__ float sT[NN * 32];     // 16 KB: s[i][j0..j0+31]

    const int bm = blockIdx.x >> 2;
    const int jc = blockIdx.x & 3;
    const int j0 = jc * 32;
    const int tid = threadIdx.x;

    const int Nv = g_nv[bm];
    float* outb = out + bm * (NN * DD) + j0 * DD;
    if (j0 >= Nv) {     // fully masked tile: zero 32 j x 32 d = 256 float4
        if (tid < 256) ((float4*)outb)[tid] = make_float4(0.f, 0.f, 0.f, 0.f);
        return;
    }

    // stage x1 (full) and the s column-tile (rows < Nv)
    {
        const float4* x1g4 = (const float4*)(g_x1 + bm * (NN * DD));
        #pragma unroll
        for (int idx = tid; idx < 1024; idx += 512) ((float4*)x1s)[idx] = x1g4[idx];
        const int nrow4 = Nv * 8;     // 8 float4 per 32-j row
        const float* sg = g_s + bm * (NN * NN) + j0;
        for (int idx = tid; idx < nrow4; idx += 512) {
            int row = idx >> 3, c4 = idx & 7;
            ((float4*)sT)[row * 8 + c4] = ((const float4*)(sg + row * NN))[c4];
        }
    }
    __syncthreads();

    // thread: jj = tid>>4 (0..31), d2 = tid&15 -> outputs (jj, 2*d2), (jj, 2*d2+1)
    const int jj = tid >> 4;
    const int d2 = tid & 15;
    const u64* x1p = (const u64*)x1s + d2;    // packed float2 per row (stride 16 u64)
    const float* sp = sT + jj;
    u64 acc = f2pack(0.f, 0.f);
    for (int i = 0; i < Nv; i++) {
        float s = sp[i * 32];
        acc = f2fma(f2pack(s, s), x1p[i * 16], acc);
    }
    float al, ah; f2unpack(al, ah, acc);
    const int gj = j0 + jj;
    const float m  = g_mask[bm * NN + gj];
    const float bb = b3[0];
    const int gidx = bm * (NN * DD) + gj * DD + 2 * d2;
    float2 o;
    o.x = (al + bb + x[gidx    ]) * m;
    o.y = (ah + bb + x[gidx + 1]) * m;
    *(float2*)(out + gidx) = o;
}

// ---------------------------------------------------------------------------
extern "C" void kernel_launch(void* const* d_in, const int* in_sizes, int n_in,
                              void* d_out, int out_size)
{
    (void)in_sizes; (void)n_in; (void)out_size;
    const float* x    = (const float*)d_in[0];
    const float* xsz  = (const float*)d_in[1];
    const float* W1a  = (const float*)d_in[2];
    const float* b1a  = (const float*)d_in[3];
    const float* W1b  = (const float*)d_in[4];
    const float* b1b  = (const float*)d_in[5];
    const float* W2a  = (const float*)d_in[6];
    const float* b2a  = (const float*)d_in[7];
    const float* W2b  = (const float*)d_in[8];
    const float* b2b  = (const float*)d_in[9];
    const float* w3   = (const float*)d_in[10];
    const float* b3   = (const float*)d_in[11];
    float* out = (float*)d_out;

    k1 <<<NSET * 8, 256>>>(x, xsz, W1a, b1a, W1b, b1b, W2a);
    k2a<<<NSET * 16, 512>>>(b2a, W2b, b2b, w3);
    k2b<<<NSET * 4, 512>>>(x, b3, out);
}

// round 15
// speedup vs baseline: 1.1689x; 1.1689x over previous
#include <cuda_runtime.h>

// Problem constants: B=4, M=8, N=128, D=32, 2D=64, H=64. BM = B*M = 32 sets.
#define NSET 32
#define NN   128
#define DD   32
#define DD2  64

// Padded strides: 17 float4 = 272 B row stride => 4-bank skew, conflict-free.
#define A1S_STRIDE4 17
#define DS_STRIDE   68

typedef unsigned long long u64;

// Scratch (device globals -- no allocation allowed)
__device__ float g_x1[NSET * NN * DD];
__device__ float g_A1[NSET * NN * DD2];
__device__ float g_A2[NSET * NN * DD2];
__device__ float g_mask[NSET * NN];
__device__ int   g_nv[NSET];               // valid prefix length per set

// ---------------- packed f32x2 helpers (sm_103a) ----------------
__device__ __forceinline__ u64 f2add(u64 a, u64 b) {
    u64 r; asm("add.rn.f32x2 %0,%1,%2;" : "=l"(r) : "l"(a), "l"(b)); return r;
}
__device__ __forceinline__ u64 f2mul(u64 a, u64 b) {
    u64 r; asm("mul.rn.f32x2 %0,%1,%2;" : "=l"(r) : "l"(a), "l"(b)); return r;
}
__device__ __forceinline__ u64 f2fma(u64 a, u64 b, u64 c) {
    u64 r; asm("fma.rn.f32x2 %0,%1,%2,%3;" : "=l"(r) : "l"(a), "l"(b), "l"(c)); return r;
}
__device__ __forceinline__ u64 f2pack(float lo, float hi) {
    u64 r; asm("mov.b64 %0,{%1,%2};" : "=l"(r) : "f"(lo), "f"(hi)); return r;
}
__device__ __forceinline__ void f2unpack(float& lo, float& hi, u64 v) {
    asm("mov.b64 {%0,%1},%2;" : "=f"(lo), "=f"(hi) : "l"(v));
}
__device__ __forceinline__ float tanh_ap(float x) {
    float r; asm("tanh.approx.f32 %0,%1;" : "=f"(r) : "f"(x)); return r;
}

// scalar gelu (jax tanh form) via tanh.approx.
__device__ __forceinline__ float gelu_f(float t) {
    float u  = t * t;
    float z  = t * fmaf(0.0356774081f, u, 0.7978845608f);
    float th = tanh_ap(z);
    float ht = 0.5f * t;
    return fmaf(th, ht, ht);
}

// Nonlinear part of gelu-dot: packed math computes z and w = 0.5*v*t;
// scalar FMAs accumulate tanh(z)*w. Linear part factored into P[i]+Q[j].
__device__ __forceinline__ void gelu2_nl2(u64 a, u64 d, u64 hv,
                                          float& accl, float& acch,
                                          u64 C1, u64 C2) {
    u64 t = f2add(a, d);
    u64 u = f2mul(t, t);
    u64 p = f2fma(C1, u, C2);
    u64 z = f2mul(t, p);
    u64 w = f2mul(t, hv);
    float zl, zh; f2unpack(zl, zh, z);
    float wl, wh; f2unpack(wl, wh, w);
    accl = fmaf(tanh_ap(zl), wl, accl);
    acch = fmaf(tanh_ap(zh), wh, acch);
}

// ---------------------------------------------------------------------------
// Kernel 1: per-set norm stats + set_norm + MLP1 + A1/A2 precompute + Nv.
// grid = NSET * 8 blocks (one set x 16 rows each), 256 threads.
// GEMM phases register-blocked 1x4 with LDS.128 weight loads.
// ---------------------------------------------------------------------------
__global__ __launch_bounds__(256) void k1(
    const float* __restrict__ x, const float* __restrict__ x_size,
    const float* __restrict__ W1a, const float* __restrict__ b1a,
    const float* __restrict__ W1b, const float* __restrict__ b1b,
    const float* __restrict__ W2a)
{
    __shared__ float xs[NN * DD];           // staging; later hb (1024) + x1b (512)
    __shared__ float w1a[DD * DD2];
    __shared__ float w1b[DD2 * DD];
    __shared__ float w2a[DD * DD2];
    __shared__ float xn[16 * DD];
    __shared__ float maskS[NN];
    __shared__ float red[8];
    __shared__ float statS[2];

    const int bm   = blockIdx.x >> 3;
    const int tile = blockIdx.x & 7;
    const int r0   = tile * 16;
    const int tid  = threadIdx.x;

    const float4* xg  = (const float4*)(x + bm * (NN * DD));
    float4*       xs4 = (float4*)xs;
    float lsum = 0.f;
    #pragma unroll
    for (int i = tid; i < 1024; i += 256) {
        float4 v = xg[i];
        xs4[i] = v;
        lsum += v.x + v.y + v.z + v.w;
    }
    #pragma unroll
    for (int i = tid; i < 512; i += 256) ((float4*)w1a)[i] = ((const float4*)W1a)[i];
    #pragma unroll
    for (int i = tid; i < 512; i += 256) ((float4*)w1b)[i] = ((const float4*)W1b)[i];
    #pragma unroll
    for (int i = tid; i < 512; i += 256) ((float4*)w2a)[i] = ((const float4*)W2a)[i];
    __syncthreads();

    // item mask (vectorized float4 compares; respects -0.0 == 0.0)
    if (tid < NN) {
        const float4* row4 = (const float4*)(xs + tid * DD);
        bool nz = false;
        #pragma unroll
        for (int e = 0; e < 8; e++) {
            float4 v = row4[e];
            nz = nz || (v.x != 0.f) || (v.y != 0.f) || (v.z != 0.f) || (v.w != 0.f);
        }
        maskS[tid] = nz ? 1.f : 0.f;
    }
    #pragma unroll
    for (int o = 16; o; o >>= 1) lsum += __shfl_xor_sync(0xffffffffu, lsum, o);
    if ((tid & 31) == 0) red[tid >> 5] = lsum;
    __syncthreads();
    const float denom = x_size[bm >> 3] * (float)DD;
    if (tid == 0) {
        float s = 0.f;
        #pragma unroll
        for (int w = 0; w < 8; w++) s += red[w];
        statS[0] = s / denom;
    }
    // Nv = 1 + last index with mask=1 (maskS visible after the barrier above)
    if (tid < 32) {
        int mx = -1;
        #pragma unroll
        for (int c = 0; c < 4; c++) {
            unsigned bal = __ballot_sync(0xffffffffu, maskS[c * 32 + tid] != 0.f);
            if (bal) { int hi = 31 - __clz((int)bal); if (c * 32 + hi > mx) mx = c * 32 + hi; }
        }
        if (tid == 0) g_nv[bm] = mx + 1;
    }
    __syncthreads();
    const float mean = statS[0];

    float lss = 0.f;
    #pragma unroll
    for (int i = tid; i < 1024; i += 256) {
        float4 v = xs4[i];
        float m = maskS[i >> 3];
        float a = v.x - mean, b = v.y - mean, c = v.z - mean, d = v.w - mean;
        lss += (a * a + b * b + c * c + d * d) * m;
    }
    #pragma unroll
    for (int o = 16; o; o >>= 1) lss += __shfl_xor_sync(0xffffffffu, lss, o);
    if ((tid & 31) == 0) red[tid >> 5] = lss;
    __syncthreads();
    if (tid == 0) {
        float s = 0.f;
        #pragma unroll
        for (int w = 0; w < 8; w++) s += red[w];
        statS[1] = 1.0f / (sqrtf(s / denom) + 1e-8f);
    }
    __syncthreads();
    const float inv = statS[1];

    #pragma unroll
    for (int i = tid; i < 512; i += 256) {
        int n = r0 + (i >> 5);
        int e = i & 31;
        xn[i] = (xs[n * DD + e] - mean) * inv * maskS[n];
    }
    if (tid < 16) g_mask[bm * NN + r0 + tid] = maskS[r0 + tid];
    __syncthreads();

    float* hb  = xs;          // 16*64
    float* x1b = xs + 1024;   // 16*32
    const int n  = tid >> 4;      // 0..15 (local row)
    const int kq = tid & 15;      // quad index

    // --- hidden = gelu(xn @ W1a + b1a): thread -> (n, k0=kq*4..+3) ---
    {
        const float4* w1a4 = (const float4*)w1a;
        float4 acc = ((const float4*)b1a)[kq];
        const float* xr = xn + n * DD;
        #pragma unroll
        for (int e = 0; e < DD; e++) {
            float xv  = xr[e];
            float4 w  = w1a4[e * 16 + kq];
            acc.x = fmaf(xv, w.x, acc.x);
            acc.y = fmaf(xv, w.y, acc.y);
            acc.z = fmaf(xv, w.z, acc.z);
            acc.w = fmaf(xv, w.w, acc.w);
        }
        float4 g;
        g.x = gelu_f(acc.x); g.y = gelu_f(acc.y);
        g.z = gelu_f(acc.z); g.w = gelu_f(acc.w);
        ((float4*)hb)[n * 16 + kq] = g;
    }
    __syncthreads();

    // --- x1 = (hidden @ W1b + b1b) * mask: thread -> (n, d0=kq*2, d0+1) ---
    {
        const float2* w1b2 = (const float2*)w1b;
        float2 acc = ((const float2*)b1b)[kq];
        const float* hr = hb + n * DD2;
        #pragma unroll
        for (int k = 0; k < DD2; k++) {
            float h  = hr[k];
            float2 w = w1b2[k * 16 + kq];
            acc.x = fmaf(h, w.x, acc.x);
            acc.y = fmaf(h, w.y, acc.y);
        }
        float m = maskS[r0 + n];
        acc.x *= m; acc.y *= m;
        ((float2*)x1b)[n * 16 + kq] = acc;
        *(float2*)(g_x1 + bm * (NN * DD) + (r0 + n) * DD + kq * 2) = acc;
    }
    __syncthreads();

    // --- A1 = x1 @ W2a, A2 = xn @ W2a: thread -> (n, k0=kq*4..+3), both ---
    {
        const float4* w2a4 = (const float4*)w2a;
        float4 a1 = make_float4(0.f, 0.f, 0.f, 0.f);
        float4 a2 = make_float4(0.f, 0.f, 0.f, 0.f);
        const float* x1r = x1b + n * DD;
        const float* xnr = xn  + n * DD;
        #pragma unroll
        for (int e = 0; e < DD; e++) {
            float xa = x1r[e];
            float xb = xnr[e];
            float4 w = w2a4[e * 16 + kq];
            a1.x = fmaf(xa, w.x, a1.x); a1.y = fmaf(xa, w.y, a1.y);
            a1.z = fmaf(xa, w.z, a1.z); a1.w = fmaf(xa, w.w, a1.w);
            a2.x = fmaf(xb, w.x, a2.x); a2.y = fmaf(xb, w.y, a2.y);
            a2.z = fmaf(xb, w.z, a2.z); a2.w = fmaf(xb, w.w, a2.w);
        }
        const int go = bm * (NN * DD2) + (r0 + n) * DD2 + kq * 4;
        *(float4*)(g_A1 + go) = a1;
        *(float4*)(g_A2 + go) = a2;
    }
}

// ---------------------------------------------------------------------------
// Kernel 2: pair scores + aggregation with valid-size truncation (R12 best).
// grid = NSET * 8 (one set x 16 j's), 512 threads, 2 CTAs/SM.
// ---------------------------------------------------------------------------
__global__ __launch_bounds__(512, 2) void k2(
    const float* __restrict__ x,
    const float* __restrict__ b2a, const float* __restrict__ W2b,
    const float* __restrict__ b2b, const float* __restrict__ w3,
    const float* __restrict__ b3, float* __restrict__ out)
{
    __shared__ float A1s[NN * A1S_STRIDE4 * 4];   // padded rows; reused as x1s later
    __shared__ float dS[16 * DS_STRIDE];
    __shared__ float vS[DD2];
    __shared__ float sS[NN * 16];
    __shared__ float PS[NN];
    __shared__ float QS[16];
    __shared__ float cS;

    const int bm = blockIdx.x >> 3;
    const int jt = blockIdx.x & 7;
    const int j0 = jt * 16;
    const int tid = threadIdx.x;

    const int Nv = g_nv[bm];
    if (j0 >= Nv) {
        if (tid < 128) {
            float4 z4 = make_float4(0.f, 0.f, 0.f, 0.f);
            ((float4*)(out + bm * (NN * DD) + j0 * DD))[tid] = z4;
        }
        return;
    }
    const int nr   = min(4, max(2, (Nv + 31) >> 5));
    const int aggN = nr * 32;

    const float4* a1g  = (const float4*)(g_A1 + bm * (NN * DD2));
    float4*       A1s4 = (float4*)A1s;
    #pragma unroll
    for (int idx = tid; idx < 2048; idx += 512) {
        int i  = idx >> 4;
        int k4 = idx & 15;
        A1s4[i * A1S_STRIDE4 + k4] = a1g[idx];
    }
    #pragma unroll
    for (int i = tid; i < 1024; i += 512) {
        int jj = i >> 6, k = i & 63;
        dS[jj * DS_STRIDE + k] = b2a[k] - g_A2[bm * (NN * DD2) + (j0 + jj) * DD2 + k];
    }
    if (tid >= 448) {
        int kk = tid - 448;
        float acc = 0.f;
        #pragma unroll
        for (int h = 0; h < 64; h++) acc = fmaf(W2b[kk * 64 + h], w3[h], acc);
        vS[kk] = 0.5f * acc;
    }
    if (tid == 0) {
        float acc = 0.f;
        #pragma unroll
        for (int h = 0; h < 64; h++) acc = fmaf(b2b[h], w3[h], acc);
        cS = acc;
    }
    __syncthreads();

    if (tid < NN) {
        const float* row = A1s + tid * (A1S_STRIDE4 * 4);
        float acc = 0.f;
        #pragma unroll
        for (int k = 0; k < DD2; k++) acc = fmaf(row[k], vS[k], acc);
        PS[tid] = acc;
    } else if (tid < NN + 16) {
        int jj = tid - NN;
        const float* row = dS + jj * DS_STRIDE;
        float acc = 0.f;
        #pragma unroll
        for (int k = 0; k < DD2; k++) acc = fmaf(row[k], vS[k], acc);
        QS[jj] = acc;
    }
    __syncthreads();

    const int j  = tid & 15;
    const int bi = tid >> 4;
    const ulonglong2* A1s2 = (const ulonglong2*)A1s;
    const ulonglong2* dj2  = (const ulonglong2*)(dS + j * DS_STRIDE);
    const ulonglong2* vv2  = (const ulonglong2*)vS;

    const u64 C1 = f2pack(0.0356774081f, 0.0356774081f);
    const u64 C2 = f2pack(0.7978845608f, 0.7978845608f);

    float a0l = 0.f, a0h = 0.f, a1l = 0.f, a1h = 0.f;
    float a2l = 0.f, a2h = 0.f, a3l = 0.f, a3h = 0.f;
    const bool g2 = (nr >= 3), g3 = (nr >= 4);
    #pragma unroll
    for (int k4 = 0; k4 < 16; k4++) {
        ulonglong2 dd = dj2[k4];
        ulonglong2 hv = vv2[k4];
        ulonglong2 q;
        q = A1s2[(bi      ) * A1S_STRIDE4 + k4];
        gelu2_nl2(q.x, dd.x, hv.x, a0l, a0h, C1, C2);
        gelu2_nl2(q.y, dd.y, hv.y, a0l, a0h, C1, C2);
        q = A1s2[(bi + 32) * A1S_STRIDE4 + k4];
        gelu2_nl2(q.x, dd.x, hv.x, a1l, a1h, C1, C2);
        gelu2_nl2(q.y, dd.y, hv.y, a1l, a1h, C1, C2);
        if (g2) {
            q = A1s2[(bi + 64) * A1S_STRIDE4 + k4];
            gelu2_nl2(q.x, dd.x, hv.x, a2l, a2h, C1, C2);
            gelu2_nl2(q.y, dd.y, hv.y, a2l, a2h, C1, C2);
        }
        if (g3) {
            q = A1s2[(bi + 96) * A1S_STRIDE4 + k4];
            gelu2_nl2(q.x, dd.x, hv.x, a3l, a3h, C1, C2);
            gelu2_nl2(q.y, dd.y, hv.y, a3l, a3h, C1, C2);
        }
    }
    {
        const float base = cS + QS[j];
        sS[(bi      ) * 16 + j] = base + PS[bi      ] + a0l + a0h;
        sS[(bi + 32) * 16 + j] = base + PS[bi + 32] + a1l + a1h;
        if (g2) sS[(bi + 64) * 16 + j] = base + PS[bi + 64] + a2l + a2h;
        if (g3) sS[(bi + 96) * 16 + j] = base + PS[bi + 96] + a3l + a3h;
    }
    __syncthreads();

    float* x1s = A1s;
    {
        const float4* x1g4 = (const float4*)(g_x1 + bm * (NN * DD));
        #pragma unroll
        for (int idx = tid; idx < 1024; idx += 512) ((float4*)x1s)[idx] = x1g4[idx];
    }
    __syncthreads();

    {
        const int jj = tid >> 5;
        const int d  = tid & 31;
        const float* sp = sS + jj;
        float acc = 0.f;
        #pragma unroll 4
        for (int i = 0; i < aggN; i++) acc = fmaf(sp[i * 16], x1s[i * DD + d], acc);
        const int gj   = j0 + jj;
        const int gidx = bm * (NN * DD) + gj * DD + d;
        out[gidx] = (acc + b3[0] + x[gidx]) * g_mask[bm * NN + gj];
    }
}

// ---------------------------------------------------------------------------
extern "C" void kernel_launch(void* const* d_in, const int* in_sizes, int n_in,
                              void* d_out, int out_size)
{
    (void)in_sizes; (void)n_in; (void)out_size;
    const float* x    = (const float*)d_in[0];
    const float* xsz  = (const float*)d_in[1];
    const float* W1a  = (const float*)d_in[2];
    const float* b1a  = (const float*)d_in[3];
    const float* W1b  = (const float*)d_in[4];
    const float* b1b  = (const float*)d_in[5];
    const float* W2a  = (const float*)d_in[6];
    const float* b2a  = (const float*)d_in[7];
    const float* W2b  = (const float*)d_in[8];
    const float* b2b  = (const float*)d_in[9];
    const float* w3   = (const float*)d_in[10];
    const float* b3   = (const float*)d_in[11];
    float* out = (float*)d_out;

    k1<<<NSET * 8, 256>>>(x, xsz, W1a, b1a, W1b, b1b, W2a);
    k2<<<NSET * 8, 512>>>(x, b2a, W2b, b2b, w3, b3, out);
}